// round 14
// baseline (speedup 1.0000x reference)
#include <cuda_runtime.h>
#include <cstdint>

#define NN 100000
#define NE 1000000
#define HID 64
#define NB 391      // ceil(NN/256)
#define CAP 96      // max degree capacity (Poisson(10): P(deg>=96) ~ 0)
#define GRIDB 1563  // ceil(NN/64)

typedef unsigned long long u64;

// ---------------- device scratch ----------------
__device__ float g_P[(size_t)NN * HID];
__device__ float g_xs[3][(size_t)NN * HID];
__device__ int   g_cnt[NN];                        // cursor -> degree
__device__ int2  g_pay[(size_t)NN * CAP];          // (src, weight-bits) buckets
__device__ int   g_is64;

// ---------------- f32x2 packed helpers --------------------------------------
__device__ __forceinline__ u64 pk2(float x, float y) {
    u64 r; asm("mov.b64 %0,{%1,%2};" : "=l"(r) : "f"(x), "f"(y)); return r;
}
__device__ __forceinline__ void up2(u64 v, float& x, float& y) {
    asm("mov.b64 {%0,%1},%2;" : "=f"(x), "=f"(y) : "l"(v));
}
__device__ __forceinline__ u64 ff2(u64 a, u64 b, u64 c) {
    u64 d; asm("fma.rn.f32x2 %0,%1,%2,%3;" : "=l"(d) : "l"(a), "l"(b), "l"(c));
    return d;
}

// ---------------- init: zero counts + dtype detection ------------------------
__global__ void init_k(const int* __restrict__ ei) {
    int i = blockIdx.x * 256 + threadIdx.x;
    if (i < NN) g_cnt[i] = 0;
    if (i == 0) {
        int is64 = 1;
        for (int e = 0; e < 64; e++)
            if (ei[2 * e + 1] != 0) { is64 = 0; break; }
        g_is64 = is64;
    }
}

__device__ __forceinline__ int load_dst(const int* ei, int e) {
    return g_is64 ? (int)((const long long*)ei)[NE + e] : ei[NE + e];
}
__device__ __forceinline__ int load_src(const int* ei, int e) {
    return g_is64 ? (int)((const long long*)ei)[e] : ei[e];
}

// ---------------- fused layer kernel -----------------------------------------
// Per 64-node tile: A-stage aggregates in-place
//   As[r][ch] = relu(bn((1+eps)*P[m] + sum_e w_e * P[src_e]))
// then GEMM: xs = relu(As @ W2 + b2).
// 1024 (node, ch4) tasks / 256 threads = 4 tasks/thread.
__global__ __launch_bounds__(256) void layer_k(
    const float* __restrict__ P, const float* __restrict__ W2,
    const float* __restrict__ b1, const float* __restrict__ gam,
    const float* __restrict__ bet, const float* __restrict__ mean,
    const float* __restrict__ var, const float* __restrict__ epsp,
    const float* __restrict__ b2, float* __restrict__ xs) {
    constexpr int K = 64, NOUT = 64, BM = 64, KP = 68, CG = 16, RPT = 4;

    extern __shared__ float sm[];
    float* As = sm;                  // 64 x 68
    float* Bs = As + BM * KP;        // 64 x 64
    float* sc = Bs + K * NOUT;       // 64
    float* sh = sc + 64;             // 64

    int tid = threadIdx.x;
    int m0 = blockIdx.x * BM;

    if (tid < 64) {
        float s = gam[tid] * rsqrtf(var[tid] + 1e-5f);
        sc[tid] = s;
        sh[tid] = (b1[tid] - mean[tid]) * s + bet[tid];
    }
    // stage B while A-stage runs (no dependence)
    for (int i = tid; i < K * NOUT / 4; i += 256)
        ((float4*)Bs)[i] = ((const float4*)W2)[i];
    __syncthreads();   // sc/sh ready

    float ev = 1.0f + epsp[0];

    // ---- A-stage: aggregation + BN/ReLU, straight into smem ----
#pragma unroll
    for (int j = 0; j < 4; j++) {
        int task = j * 256 + tid;
        int r = task >> 4;            // node within tile
        int ch = (task & 15) * 4;     // channel group
        int m = m0 + r;
        float4 o = make_float4(0.f, 0.f, 0.f, 0.f);
        if (m < NN) {
            int d = g_cnt[m];
            size_t base = (size_t)m * CAP;
            float4 acc = make_float4(0.f, 0.f, 0.f, 0.f);
            for (int e = 0; e < d; e++) {
                int2 pw = __ldg(&g_pay[base + e]);   // same addr across 16 thr: L1 bcast
                float w = __int_as_float(pw.y);
                float4 v = *(const float4*)(P + (size_t)pw.x * HID + ch);
                acc.x = fmaf(w, v.x, acc.x);
                acc.y = fmaf(w, v.y, acc.y);
                acc.z = fmaf(w, v.z, acc.z);
                acc.w = fmaf(w, v.w, acc.w);
            }
            float4 p = *(const float4*)(P + (size_t)m * HID + ch);
            o.x = fmaxf(fmaf(fmaf(ev, p.x, acc.x), sc[ch + 0], sh[ch + 0]), 0.f);
            o.y = fmaxf(fmaf(fmaf(ev, p.y, acc.y), sc[ch + 1], sh[ch + 1]), 0.f);
            o.z = fmaxf(fmaf(fmaf(ev, p.z, acc.z), sc[ch + 2], sh[ch + 2]), 0.f);
            o.w = fmaxf(fmaf(fmaf(ev, p.w, acc.w), sc[ch + 3], sh[ch + 3]), 0.f);
        }
        *(float4*)(As + r * KP + ch) = o;
    }
    __syncthreads();

    // ---- mainloop ----
    int tx = tid % CG, ty = tid / CG;
    u64 acc[RPT][2] = {};
#pragma unroll 4
    for (int k = 0; k < K; k += 2) {
        ulonglong2 b0 = *(const ulonglong2*)(Bs + k * NOUT + tx * 4);
        ulonglong2 b1v = *(const ulonglong2*)(Bs + (k + 1) * NOUT + tx * 4);
        float2 a[RPT];
#pragma unroll
        for (int i = 0; i < RPT; i++)
            a[i] = *(const float2*)(As + (ty * RPT + i) * KP + k);
#pragma unroll
        for (int i = 0; i < RPT; i++) {
            u64 ap0 = pk2(a[i].x, a[i].x);
            acc[i][0] = ff2(ap0, b0.x, acc[i][0]);
            acc[i][1] = ff2(ap0, b0.y, acc[i][1]);
            u64 ap1 = pk2(a[i].y, a[i].y);
            acc[i][0] = ff2(ap1, b1v.x, acc[i][0]);
            acc[i][1] = ff2(ap1, b1v.y, acc[i][1]);
        }
    }

    float4 bb = *(const float4*)(b2 + tx * 4);
#pragma unroll
    for (int i = 0; i < RPT; i++) {
        int m = m0 + ty * RPT + i;
        if (m < NN) {
            float4 o;
            up2(acc[i][0], o.x, o.y);
            up2(acc[i][1], o.z, o.w);
            o.x = fmaxf(o.x + bb.x, 0.f); o.y = fmaxf(o.y + bb.y, 0.f);
            o.z = fmaxf(o.z + bb.z, 0.f); o.w = fmaxf(o.w + bb.w, 0.f);
            *(float4*)(xs + (size_t)m * NOUT + tx * 4) = o;
        }
    }
}

// ---------------- plain GEMM kernel ------------------------------------------
// MODE 0: Out = A0 @ B
// MODE 2: A = concat(A0,A1,A2); Out = A @ B + bias2
// SCAT: blocks >= GRIDB perform the edge scatter (bucket alloc via atomicAdd)
template <int K, int NOUT, int MODE, int SCAT>
__global__ __launch_bounds__(256) void gemm_k(
    const float* __restrict__ A0, const float* __restrict__ A1,
    const float* __restrict__ A2, const float* __restrict__ B,
    const float* __restrict__ bias2, float* __restrict__ Out,
    const int* __restrict__ ei, const float* __restrict__ ew) {
    constexpr int BM = 64;
    constexpr int KP = K + 4;
    constexpr int CG = NOUT / 4;
    constexpr int RPT = (BM * CG) / 256;

    if constexpr (SCAT) {
        int sb = (int)blockIdx.x - GRIDB;
        if (sb >= 0) {
            int e = sb * 256 + threadIdx.x;
            if (e < NE) {
                int dst = load_dst(ei, e);
                int src = load_src(ei, e);
                int p = atomicAdd(&g_cnt[dst], 1);
                if (p < CAP)
                    g_pay[(size_t)dst * CAP + p] =
                        make_int2(src, __float_as_int(ew[e]));
            }
            return;
        }
    }

    extern __shared__ float sm[];
    float* As = sm;
    float* Bs = As + BM * KP;

    int tid = threadIdx.x;
    int m0 = blockIdx.x * BM;

    for (int i = tid; i < BM * (K / 4); i += 256) {
        int r = i / (K / 4), c4 = i % (K / 4);
        int m = m0 + r;
        float4 v = make_float4(0.f, 0.f, 0.f, 0.f);
        if (m < NN) {
            if constexpr (MODE == 2) {
                int ch = c4 * 4;
                const float* src = (ch < 64) ? A0 : (ch < 128 ? A1 : A2);
                v = *(const float4*)(src + (size_t)m * HID + (ch & 63));
            } else {
                v = *(const float4*)(A0 + (size_t)m * K + c4 * 4);
            }
        }
        *(float4*)(As + r * KP + c4 * 4) = v;
    }
    for (int i = tid; i < K * NOUT / 4; i += 256)
        ((float4*)Bs)[i] = ((const float4*)B)[i];
    __syncthreads();

    int tx = tid % CG, ty = tid / CG;
    u64 acc[RPT][2] = {};

#pragma unroll 4
    for (int k = 0; k < K; k += 2) {
        ulonglong2 b0 = *(const ulonglong2*)(Bs + k * NOUT + tx * 4);
        ulonglong2 b1 = *(const ulonglong2*)(Bs + (k + 1) * NOUT + tx * 4);
        float2 a[RPT];
#pragma unroll
        for (int i = 0; i < RPT; i++)
            a[i] = *(const float2*)(As + (ty * RPT + i) * KP + k);
#pragma unroll
        for (int i = 0; i < RPT; i++) {
            u64 ap0 = pk2(a[i].x, a[i].x);
            acc[i][0] = ff2(ap0, b0.x, acc[i][0]);
            acc[i][1] = ff2(ap0, b0.y, acc[i][1]);
            u64 ap1 = pk2(a[i].y, a[i].y);
            acc[i][0] = ff2(ap1, b1.x, acc[i][0]);
            acc[i][1] = ff2(ap1, b1.y, acc[i][1]);
        }
    }

    float4 bb = make_float4(0.f, 0.f, 0.f, 0.f);
    if constexpr (MODE == 2) bb = *(const float4*)(bias2 + tx * 4);

#pragma unroll
    for (int i = 0; i < RPT; i++) {
        int m = m0 + ty * RPT + i;
        if (m < NN) {
            float4 o;
            up2(acc[i][0], o.x, o.y);
            up2(acc[i][1], o.z, o.w);
            o.x += bb.x; o.y += bb.y; o.z += bb.z; o.w += bb.w;
            *(float4*)(Out + (size_t)m * NOUT + tx * 4) = o;
        }
    }
}

// ---------------- host launcher ---------------------------------------------
extern "C" void kernel_launch(void* const* d_in, const int* in_sizes, int n_in,
                              void* d_out, int out_size) {
    const float* x    = (const float*)d_in[0];
    const int*   ei   = (const int*)d_in[1];
    const float* ew   = (const float*)d_in[2];
    const float* eps  = (const float*)d_in[3];
    const float* W1_0 = (const float*)d_in[4];
    const float* b1_0 = (const float*)d_in[5];
    const float* W1_r = (const float*)d_in[6];
    const float* b1_r = (const float*)d_in[7];
    const float* W2   = (const float*)d_in[8];
    const float* b2   = (const float*)d_in[9];
    const float* gam  = (const float*)d_in[10];
    const float* bet  = (const float*)d_in[11];
    const float* mean = (const float*)d_in[12];
    const float* var  = (const float*)d_in[13];
    const float* l2W  = (const float*)d_in[14];
    const float* l2b  = (const float*)d_in[15];
    float* out = (float*)d_out;

    float *P, *XS;
    cudaGetSymbolAddress((void**)&P, g_P);
    cudaGetSymbolAddress((void**)&XS, g_xs);
    float* xs0 = XS;
    float* xs1 = XS + (size_t)NN * HID;
    float* xs2 = XS + 2 * (size_t)NN * HID;

    const int SM_128_64 = (64 * 132 + 128 * 64) * 4;        // 66560
    const int SM_64_64  = (64 * 68 + 64 * 64) * 4;          // 33792
    const int SM_LAYER  = (64 * 68 + 64 * 64 + 128) * 4;    // 34304
    const int SM_192_32 = (64 * 196 + 192 * 32) * 4;        // 74752

    cudaFuncSetAttribute((const void*)gemm_k<128, 64, 0, 1>,
                         cudaFuncAttributeMaxDynamicSharedMemorySize, SM_128_64);
    cudaFuncSetAttribute((const void*)gemm_k<192, 32, 2, 0>,
                         cudaFuncAttributeMaxDynamicSharedMemorySize, SM_192_32);

    const int EBL = (NE + 255) / 256;      // 3907

    // ----- init + fused {input projection || edge scatter} -----
    init_k<<<NB, 256>>>(ei);
    gemm_k<128, 64, 0, 1><<<GRIDB + EBL, 256, SM_128_64>>>(
        x, 0, 0, W1_0, 0, P, ei, ew);

    // ----- layer 0 (agg fused into GEMM A-stage) -----
    layer_k<<<GRIDB, 256, SM_LAYER>>>(P, W2, b1_0, gam, bet, mean, var,
                                      eps, b2, xs0);
    // ----- layer 1 -----
    gemm_k<64, 64, 0, 0><<<GRIDB, 256, SM_64_64>>>(
        xs0, 0, 0, W1_r, 0, P, 0, 0);
    layer_k<<<GRIDB, 256, SM_LAYER>>>(P, W2 + 4096, b1_r, gam + 64, bet + 64,
                                      mean + 64, var + 64, eps + 1, b2 + 64, xs1);
    // ----- layer 2 -----
    gemm_k<64, 64, 0, 0><<<GRIDB, 256, SM_64_64>>>(
        xs1, 0, 0, W1_r + 4096, 0, P, 0, 0);
    layer_k<<<GRIDB, 256, SM_LAYER>>>(P, W2 + 8192, b1_r + 64, gam + 128,
                                      bet + 128, mean + 128, var + 128,
                                      eps + 2, b2 + 128, xs2);
    // ----- final projection (concat fused) -----
    gemm_k<192, 32, 2, 0><<<GRIDB, 256, SM_192_32>>>(
        xs0, xs1, xs2, l2W, l2b, out, 0, 0);
}

// round 15
// speedup vs baseline: 1.0261x; 1.0261x over previous
#include <cuda_runtime.h>
#include <cuda_fp16.h>
#include <cstdint>

#define NN 100000
#define NE 1000000
#define HID 64
#define NB 391      // ceil(NN/256)
#define CAP 96      // max degree capacity (Poisson(10): P(deg>=96) ~ 0)
#define GRIDB 1563  // ceil(NN/64)

typedef unsigned long long u64;

// ---------------- device scratch ----------------
__device__ float  g_P[(size_t)NN * HID];
__device__ __half g_Ph[(size_t)NN * HID];          // fp16 mirror of P (gather src)
__device__ float  g_Z[(size_t)NN * HID];           // activated (1+e)P+agg
__device__ float  g_xs[3][(size_t)NN * HID];
__device__ int    g_cnt[NN];                       // cursor -> degree
__device__ int2   g_pay[(size_t)NN * CAP];         // (src, weight-bits) buckets
__device__ int    g_is64;

// ---------------- f32x2 packed helpers --------------------------------------
__device__ __forceinline__ u64 pk2(float x, float y) {
    u64 r; asm("mov.b64 %0,{%1,%2};" : "=l"(r) : "f"(x), "f"(y)); return r;
}
__device__ __forceinline__ void up2(u64 v, float& x, float& y) {
    asm("mov.b64 {%0,%1},%2;" : "=f"(x), "=f"(y) : "l"(v));
}
__device__ __forceinline__ u64 ff2(u64 a, u64 b, u64 c) {
    u64 d; asm("fma.rn.f32x2 %0,%1,%2,%3;" : "=l"(d) : "l"(a), "l"(b), "l"(c));
    return d;
}

// ---------------- init: zero counts + dtype detection ------------------------
__global__ void init_k(const int* __restrict__ ei) {
    int i = blockIdx.x * 256 + threadIdx.x;
    if (i < NN) g_cnt[i] = 0;
    if (i == 0) {
        int is64 = 1;
        for (int e = 0; e < 64; e++)
            if (ei[2 * e + 1] != 0) { is64 = 0; break; }
        g_is64 = is64;
    }
}

__device__ __forceinline__ int load_dst(const int* ei, int e) {
    return g_is64 ? (int)((const long long*)ei)[NE + e] : ei[NE + e];
}
__device__ __forceinline__ int load_src(const int* ei, int e) {
    return g_is64 ? (int)((const long long*)ei)[e] : ei[e];
}

// ---------------- aggregation + fused BN/ReLU pointwise ----------------------
// 16 threads/node; payload loaded coalescedly, broadcast via half-warp shfl.
// Gather reads the fp16 mirror (128 B/row vs 256 B) -> ~halves L2 traffic.
// Epilogue: Z = relu(bn((1+eps)*P[n] + agg)), self-term in fp32.
__global__ __launch_bounds__(256) void agg_k(
    const float* __restrict__ P, float* __restrict__ Z,
    const float* __restrict__ b1, const float* __restrict__ gam,
    const float* __restrict__ bet, const float* __restrict__ mean,
    const float* __restrict__ var, const float* __restrict__ epsp) {
    int t = blockIdx.x * 256 + threadIdx.x;
    int n = t >> 4;
    int lane = threadIdx.x & 15;
    int ch = lane * 4;
    unsigned hmask = 0xFFFFu << (threadIdx.x & 16);
    size_t base = (size_t)n * CAP;
    int d = g_cnt[n];
    const __half* Ph = g_Ph;
    float4 acc = make_float4(0.f, 0.f, 0.f, 0.f);
    for (int b = 0; b < d; b += 16) {
        int idx = b + lane;
        int2 pw = (idx < d) ? __ldg(&g_pay[base + idx]) : make_int2(0, 0);
        int lim = min(d - b, 16);
#pragma unroll
        for (int jj = 0; jj < 16; jj++) {
            int srcj  = __shfl_sync(hmask, pw.x, jj, 16);
            int wbits = __shfl_sync(hmask, pw.y, jj, 16);
            if (jj < lim) {
                float wj = __int_as_float(wbits);
                uint2 hv = *(const uint2*)(Ph + (size_t)srcj * HID + ch);
                float2 f01 = __half22float2(*(const __half2*)&hv.x);
                float2 f23 = __half22float2(*(const __half2*)&hv.y);
                acc.x = fmaf(wj, f01.x, acc.x);
                acc.y = fmaf(wj, f01.y, acc.y);
                acc.z = fmaf(wj, f23.x, acc.z);
                acc.w = fmaf(wj, f23.y, acc.w);
            }
        }
    }
    // fused pointwise: relu(bn((1+eps)*p + acc))
    float ev = 1.0f + epsp[0];
    float4 p  = *(const float4*)(P + (size_t)n * HID + ch);
    float4 G  = *(const float4*)(gam + ch);
    float4 V  = *(const float4*)(var + ch);
    float4 M  = *(const float4*)(mean + ch);
    float4 B1 = *(const float4*)(b1 + ch);
    float4 BE = *(const float4*)(bet + ch);
    float sx = G.x * rsqrtf(V.x + 1e-5f);
    float sy = G.y * rsqrtf(V.y + 1e-5f);
    float sz = G.z * rsqrtf(V.z + 1e-5f);
    float sw = G.w * rsqrtf(V.w + 1e-5f);
    float4 o;
    o.x = fmaxf(fmaf(fmaf(ev, p.x, acc.x), sx, (B1.x - M.x) * sx + BE.x), 0.f);
    o.y = fmaxf(fmaf(fmaf(ev, p.y, acc.y), sy, (B1.y - M.y) * sy + BE.y), 0.f);
    o.z = fmaxf(fmaf(fmaf(ev, p.z, acc.z), sz, (B1.z - M.z) * sz + BE.z), 0.f);
    o.w = fmaxf(fmaf(fmaf(ev, p.w, acc.w), sw, (B1.w - M.w) * sw + BE.w), 0.f);
    *(float4*)(Z + (size_t)n * HID + ch) = o;
}

// ---------------- fused GEMM kernel ------------------------------------------
// MODE 0: Out = A0 @ B                      (WH: also write fp16 mirror g_Ph)
// MODE 1: Out = relu(A0 @ B + bias2)
// MODE 2: A = concat(A0,A1,A2); Out = A @ B + bias2
// SCAT: blocks >= GRIDB perform the edge scatter (bucket alloc via atomicAdd)
template <int K, int NOUT, int MODE, int SCAT, int WH>
__global__ __launch_bounds__(256) void gemm_k(
    const float* __restrict__ A0, const float* __restrict__ A1,
    const float* __restrict__ A2, const float* __restrict__ B,
    const float* __restrict__ bias2, float* __restrict__ Out,
    const int* __restrict__ ei, const float* __restrict__ ew) {
    constexpr int BM = 64;
    constexpr int KP = K + 4;
    constexpr int CG = NOUT / 4;
    constexpr int RPT = (BM * CG) / 256;

    if constexpr (SCAT) {
        int sb = (int)blockIdx.x - GRIDB;
        if (sb >= 0) {
            int e = sb * 256 + threadIdx.x;
            if (e < NE) {
                int dst = load_dst(ei, e);
                int src = load_src(ei, e);
                int p = atomicAdd(&g_cnt[dst], 1);
                if (p < CAP)
                    g_pay[(size_t)dst * CAP + p] =
                        make_int2(src, __float_as_int(ew[e]));
            }
            return;
        }
    }

    extern __shared__ float sm[];
    float* As = sm;
    float* Bs = As + BM * KP;

    int tid = threadIdx.x;
    int m0 = blockIdx.x * BM;

    for (int i = tid; i < BM * (K / 4); i += 256) {
        int r = i / (K / 4), c4 = i % (K / 4);
        int m = m0 + r;
        float4 v = make_float4(0.f, 0.f, 0.f, 0.f);
        if (m < NN) {
            if constexpr (MODE == 2) {
                int ch = c4 * 4;
                const float* src = (ch < 64) ? A0 : (ch < 128 ? A1 : A2);
                v = *(const float4*)(src + (size_t)m * HID + (ch & 63));
            } else {
                v = *(const float4*)(A0 + (size_t)m * K + c4 * 4);
            }
        }
        *(float4*)(As + r * KP + c4 * 4) = v;
    }
    for (int i = tid; i < K * NOUT / 4; i += 256)
        ((float4*)Bs)[i] = ((const float4*)B)[i];
    __syncthreads();

    int tx = tid % CG, ty = tid / CG;
    u64 acc[RPT][2] = {};

#pragma unroll 4
    for (int k = 0; k < K; k += 2) {
        ulonglong2 b0 = *(const ulonglong2*)(Bs + k * NOUT + tx * 4);
        ulonglong2 b1 = *(const ulonglong2*)(Bs + (k + 1) * NOUT + tx * 4);
        float2 a[RPT];
#pragma unroll
        for (int i = 0; i < RPT; i++)
            a[i] = *(const float2*)(As + (ty * RPT + i) * KP + k);
#pragma unroll
        for (int i = 0; i < RPT; i++) {
            u64 ap0 = pk2(a[i].x, a[i].x);
            acc[i][0] = ff2(ap0, b0.x, acc[i][0]);
            acc[i][1] = ff2(ap0, b0.y, acc[i][1]);
            u64 ap1 = pk2(a[i].y, a[i].y);
            acc[i][0] = ff2(ap1, b1.x, acc[i][0]);
            acc[i][1] = ff2(ap1, b1.y, acc[i][1]);
        }
    }

    float4 bb = make_float4(0.f, 0.f, 0.f, 0.f);
    if constexpr (MODE != 0) bb = *(const float4*)(bias2 + tx * 4);

#pragma unroll
    for (int i = 0; i < RPT; i++) {
        int m = m0 + ty * RPT + i;
        if (m < NN) {
            float4 o;
            up2(acc[i][0], o.x, o.y);
            up2(acc[i][1], o.z, o.w);
            o.x += bb.x; o.y += bb.y; o.z += bb.z; o.w += bb.w;
            if constexpr (MODE == 1) {
                o.x = fmaxf(o.x, 0.f); o.y = fmaxf(o.y, 0.f);
                o.z = fmaxf(o.z, 0.f); o.w = fmaxf(o.w, 0.f);
            }
            *(float4*)(Out + (size_t)m * NOUT + tx * 4) = o;
            if constexpr (WH) {
                __half2 h01 = __floats2half2_rn(o.x, o.y);
                __half2 h23 = __floats2half2_rn(o.z, o.w);
                uint2 hv;
                hv.x = *(const unsigned*)&h01;
                hv.y = *(const unsigned*)&h23;
                *(uint2*)(g_Ph + (size_t)m * HID + tx * 4) = hv;
            }
        }
    }
}

// ---------------- host launcher ---------------------------------------------
extern "C" void kernel_launch(void* const* d_in, const int* in_sizes, int n_in,
                              void* d_out, int out_size) {
    const float* x    = (const float*)d_in[0];
    const int*   ei   = (const int*)d_in[1];
    const float* ew   = (const float*)d_in[2];
    const float* eps  = (const float*)d_in[3];
    const float* W1_0 = (const float*)d_in[4];
    const float* b1_0 = (const float*)d_in[5];
    const float* W1_r = (const float*)d_in[6];
    const float* b1_r = (const float*)d_in[7];
    const float* W2   = (const float*)d_in[8];
    const float* b2   = (const float*)d_in[9];
    const float* gam  = (const float*)d_in[10];
    const float* bet  = (const float*)d_in[11];
    const float* mean = (const float*)d_in[12];
    const float* var  = (const float*)d_in[13];
    const float* l2W  = (const float*)d_in[14];
    const float* l2b  = (const float*)d_in[15];
    float* out = (float*)d_out;

    float *P, *Z, *XS;
    cudaGetSymbolAddress((void**)&P, g_P);
    cudaGetSymbolAddress((void**)&Z, g_Z);
    cudaGetSymbolAddress((void**)&XS, g_xs);
    float* xs0 = XS;
    float* xs1 = XS + (size_t)NN * HID;
    float* xs2 = XS + 2 * (size_t)NN * HID;

    const int SM_128_64 = (64 * 132 + 128 * 64) * 4;  // 66560
    const int SM_64_64  = (64 * 68 + 64 * 64) * 4;    // 33792
    const int SM_192_32 = (64 * 196 + 192 * 32) * 4;  // 74752

    cudaFuncSetAttribute((const void*)gemm_k<128, 64, 0, 1, 1>,
                         cudaFuncAttributeMaxDynamicSharedMemorySize, SM_128_64);
    cudaFuncSetAttribute((const void*)gemm_k<192, 32, 2, 0, 0>,
                         cudaFuncAttributeMaxDynamicSharedMemorySize, SM_192_32);

    const int EBL = (NE + 255) / 256;      // 3907
    const int AB  = (NN * 16) / 256;       // 6250 (exact)

    // ----- init + fused {input projection || edge scatter} -----
    init_k<<<NB, 256>>>(ei);
    gemm_k<128, 64, 0, 1, 1><<<GRIDB + EBL, 256, SM_128_64>>>(
        x, 0, 0, W1_0, 0, P, ei, ew);

    // ----- layer 0 -----
    agg_k<<<AB, 256>>>(P, Z, b1_0, gam, bet, mean, var, eps);
    gemm_k<64, 64, 1, 0, 0><<<GRIDB, 256, SM_64_64>>>(
        Z, 0, 0, W2, b2, xs0, 0, 0);
    // ----- layer 1 -----
    gemm_k<64, 64, 0, 0, 1><<<GRIDB, 256, SM_64_64>>>(
        xs0, 0, 0, W1_r, 0, P, 0, 0);
    agg_k<<<AB, 256>>>(P, Z, b1_r, gam + 64, bet + 64, mean + 64, var + 64,
                       eps + 1);
    gemm_k<64, 64, 1, 0, 0><<<GRIDB, 256, SM_64_64>>>(
        Z, 0, 0, W2 + 4096, b2 + 64, xs1, 0, 0);
    // ----- layer 2 -----
    gemm_k<64, 64, 0, 0, 1><<<GRIDB, 256, SM_64_64>>>(
        xs1, 0, 0, W1_r + 4096, 0, P, 0, 0);
    agg_k<<<AB, 256>>>(P, Z, b1_r + 64, gam + 128, bet + 128, mean + 128,
                       var + 128, eps + 2);
    gemm_k<64, 64, 1, 0, 0><<<GRIDB, 256, SM_64_64>>>(
        Z, 0, 0, W2 + 8192, b2 + 128, xs2, 0, 0);
    // ----- final projection (concat fused) -----
    gemm_k<192, 32, 2, 0, 0><<<GRIDB, 256, SM_192_32>>>(
        xs0, xs1, xs2, l2W, l2b, out, 0, 0);
}

// round 16
// speedup vs baseline: 1.0595x; 1.0325x over previous
#include <cuda_runtime.h>
#include <cuda_fp16.h>
#include <cstdint>

#define NN 100000
#define NE 1000000
#define HID 64
#define NB 391      // ceil(NN/256)
#define CAP 96      // max degree capacity (Poisson(10): P(deg>=96) ~ 0)
#define GRIDB 1563  // ceil(NN/64)

// ---------------- device scratch ----------------
__device__ float  g_P[(size_t)NN * HID];
__device__ __half g_Ph[(size_t)NN * HID];          // fp16 mirror of P (gather src)
__device__ float  g_Z[(size_t)NN * HID];           // activated (1+e)P+agg
__device__ float  g_xs[3][(size_t)NN * HID];
__device__ int    g_cnt[NN];                       // cursor -> degree
__device__ int2   g_pay[(size_t)NN * CAP];         // (src, weight-bits) buckets
__device__ int    g_is64;

// ---------------- init: zero counts + dtype detection ------------------------
__global__ void init_k(const int* __restrict__ ei) {
    int i = blockIdx.x * 256 + threadIdx.x;
    if (i < NN) g_cnt[i] = 0;
    if (i == 0) {
        int is64 = 1;
        for (int e = 0; e < 64; e++)
            if (ei[2 * e + 1] != 0) { is64 = 0; break; }
        g_is64 = is64;
    }
}

__device__ __forceinline__ int load_dst(const int* ei, int e) {
    return g_is64 ? (int)((const long long*)ei)[NE + e] : ei[NE + e];
}
__device__ __forceinline__ int load_src(const int* ei, int e) {
    return g_is64 ? (int)((const long long*)ei)[e] : ei[e];
}

// ---------------- aggregation + fused BN/ReLU pointwise (proven, unchanged) --
__global__ __launch_bounds__(256) void agg_k(
    const float* __restrict__ P, float* __restrict__ Z,
    const float* __restrict__ b1, const float* __restrict__ gam,
    const float* __restrict__ bet, const float* __restrict__ mean,
    const float* __restrict__ var, const float* __restrict__ epsp) {
    int t = blockIdx.x * 256 + threadIdx.x;
    int n = t >> 4;
    int lane = threadIdx.x & 15;
    int ch = lane * 4;
    unsigned hmask = 0xFFFFu << (threadIdx.x & 16);
    size_t base = (size_t)n * CAP;
    int d = g_cnt[n];
    const __half* Ph = g_Ph;
    float4 acc = make_float4(0.f, 0.f, 0.f, 0.f);
    for (int b = 0; b < d; b += 16) {
        int idx = b + lane;
        int2 pw = (idx < d) ? __ldg(&g_pay[base + idx]) : make_int2(0, 0);
        int lim = min(d - b, 16);
#pragma unroll
        for (int jj = 0; jj < 16; jj++) {
            int srcj  = __shfl_sync(hmask, pw.x, jj, 16);
            int wbits = __shfl_sync(hmask, pw.y, jj, 16);
            if (jj < lim) {
                float wj = __int_as_float(wbits);
                uint2 hv = *(const uint2*)(Ph + (size_t)srcj * HID + ch);
                float2 f01 = __half22float2(*(const __half2*)&hv.x);
                float2 f23 = __half22float2(*(const __half2*)&hv.y);
                acc.x = fmaf(wj, f01.x, acc.x);
                acc.y = fmaf(wj, f01.y, acc.y);
                acc.z = fmaf(wj, f23.x, acc.z);
                acc.w = fmaf(wj, f23.y, acc.w);
            }
        }
    }
    float ev = 1.0f + epsp[0];
    float4 p  = *(const float4*)(P + (size_t)n * HID + ch);
    float4 G  = *(const float4*)(gam + ch);
    float4 V  = *(const float4*)(var + ch);
    float4 M  = *(const float4*)(mean + ch);
    float4 B1 = *(const float4*)(b1 + ch);
    float4 BE = *(const float4*)(bet + ch);
    float sx = G.x * rsqrtf(V.x + 1e-5f);
    float sy = G.y * rsqrtf(V.y + 1e-5f);
    float sz = G.z * rsqrtf(V.z + 1e-5f);
    float sw = G.w * rsqrtf(V.w + 1e-5f);
    float4 o;
    o.x = fmaxf(fmaf(fmaf(ev, p.x, acc.x), sx, (B1.x - M.x) * sx + BE.x), 0.f);
    o.y = fmaxf(fmaf(fmaf(ev, p.y, acc.y), sy, (B1.y - M.y) * sy + BE.y), 0.f);
    o.z = fmaxf(fmaf(fmaf(ev, p.z, acc.z), sz, (B1.z - M.z) * sz + BE.z), 0.f);
    o.w = fmaxf(fmaf(fmaf(ev, p.w, acc.w), sw, (B1.w - M.w) * sw + BE.w), 0.f);
    *(float4*)(Z + (size_t)n * HID + ch) = o;
}

// ---------------- HMMA helpers -----------------------------------------------
__device__ __forceinline__ void mma16816(float* d, const unsigned* a,
                                         const unsigned* b) {
    asm volatile(
        "mma.sync.aligned.m16n8k16.row.col.f32.f16.f16.f32 "
        "{%0,%1,%2,%3}, {%4,%5,%6,%7}, {%8,%9}, {%0,%1,%2,%3};"
        : "+f"(d[0]), "+f"(d[1]), "+f"(d[2]), "+f"(d[3])
        : "r"(a[0]), "r"(a[1]), "r"(a[2]), "r"(a[3]), "r"(b[0]), "r"(b[1]));
}

// split fp32 pair into (hi, lo) fp16x2: x = hi + lo + O(eps^2)
__device__ __forceinline__ void split2(float x, float y,
                                       unsigned& h, unsigned& l) {
    __half2 hh = __floats2half2_rn(x, y);
    float2 hf = __half22float2(hh);
    __half2 ll = __floats2half2_rn(x - hf.x, y - hf.y);
    h = *reinterpret_cast<unsigned*>(&hh);
    l = *reinterpret_cast<unsigned*>(&ll);
}

// ---------------- no-smem HMMA GEMM ------------------------------------------
// D = A @ B via 3-pass split-fp16 (fp32-accurate): Ah*Bh + Ah*Bl + Al*Bh.
// 8 warps: 4(m) x 2(n); warp tile 16 x NOUT/2; K chunked by 64.
// MODE 0: plain (WH: also write fp16 mirror g_Ph)
// MODE 1: relu(D + bias2)
// MODE 2: A = concat(A0,A1,A2) via chunk->source; D + bias2
// SCAT: blocks >= GRIDB do the edge scatter instead
template <int KTOT, int NOUT, int MODE, int SCAT, int WH>
__global__ __launch_bounds__(256, 2) void gemm_k(
    const float* __restrict__ A0, const float* __restrict__ A1,
    const float* __restrict__ A2, const float* __restrict__ B,
    const float* __restrict__ bias2, float* __restrict__ Out,
    const int* __restrict__ ei, const float* __restrict__ ew) {
    if constexpr (SCAT) {
        int sb = (int)blockIdx.x - GRIDB;
        if (sb >= 0) {
            int e = sb * 256 + threadIdx.x;
            if (e < NE) {
                int dst = load_dst(ei, e);
                int src = load_src(ei, e);
                int p = atomicAdd(&g_cnt[dst], 1);
                if (p < CAP)
                    g_pay[(size_t)dst * CAP + p] =
                        make_int2(src, __float_as_int(ew[e]));
            }
            return;
        }
    }

    constexpr int NCH = KTOT / 64;        // 64-wide K chunks
    constexpr int NT  = NOUT / 16;        // n8 tiles per warp (warp covers NOUT/2)

    int lane = threadIdx.x & 31;
    int wid  = threadIdx.x >> 5;
    int wm = wid & 3, wn = wid >> 2;
    int g = lane >> 2, t = lane & 3;
    int mbase = blockIdx.x * 64 + wm * 16;
    int r0 = mbase + g, r1 = mbase + g + 8;
    int n0w = wn * (NOUT / 2);

    float acc[NT][4];
#pragma unroll
    for (int nt = 0; nt < NT; nt++)
        acc[nt][0] = acc[nt][1] = acc[nt][2] = acc[nt][3] = 0.f;

#pragma unroll
    for (int c = 0; c < NCH; c++) {
        // ---- B fragment preload (register-resident, hi/lo split) ----
        unsigned bh[4][NT][2], bl[4][NT][2];
#pragma unroll
        for (int ks = 0; ks < 4; ks++) {
#pragma unroll
            for (int nt = 0; nt < NT; nt++) {
                int k0 = c * 64 + ks * 16;
                int n = n0w + nt * 8 + g;
                float x0 = B[(k0 + 2 * t) * NOUT + n];
                float x1 = B[(k0 + 2 * t + 1) * NOUT + n];
                split2(x0, x1, bh[ks][nt][0], bl[ks][nt][0]);
                float x2 = B[(k0 + 2 * t + 8) * NOUT + n];
                float x3 = B[(k0 + 2 * t + 9) * NOUT + n];
                split2(x2, x3, bh[ks][nt][1], bl[ks][nt][1]);
            }
        }
        // ---- A source for this chunk ----
        const float* S;
        int stride;
        if constexpr (MODE == 2) {
            S = (c == 0) ? A0 : (c == 1) ? A1 : A2;
            stride = HID;
        } else {
            S = A0 + c * 64;   // column offset within row of stride KTOT
            stride = KTOT;
        }
#pragma unroll
        for (int ks = 0; ks < 4; ks++) {
            int kk = ks * 16 + 2 * t;
            float2 v00 = make_float2(0.f, 0.f), v10 = v00, v01 = v00, v11 = v00;
            if (r0 < NN) {
                v00 = *(const float2*)(S + (size_t)r0 * stride + kk);
                v01 = *(const float2*)(S + (size_t)r0 * stride + kk + 8);
            }
            if (r1 < NN) {
                v10 = *(const float2*)(S + (size_t)r1 * stride + kk);
                v11 = *(const float2*)(S + (size_t)r1 * stride + kk + 8);
            }
            unsigned ah[4], al[4];
            split2(v00.x, v00.y, ah[0], al[0]);
            split2(v10.x, v10.y, ah[1], al[1]);
            split2(v01.x, v01.y, ah[2], al[2]);
            split2(v11.x, v11.y, ah[3], al[3]);
#pragma unroll
            for (int nt = 0; nt < NT; nt++) {
                mma16816(acc[nt], ah, bh[ks][nt]);
                mma16816(acc[nt], ah, bl[ks][nt]);
                mma16816(acc[nt], al, bh[ks][nt]);
            }
        }
    }

    // ---- epilogue ----
#pragma unroll
    for (int nt = 0; nt < NT; nt++) {
        int cc = n0w + nt * 8 + 2 * t;
        float d0 = acc[nt][0], d1 = acc[nt][1];
        float d2 = acc[nt][2], d3 = acc[nt][3];
        if constexpr (MODE != 0) {
            float b0 = bias2[cc], b1v = bias2[cc + 1];
            d0 += b0; d1 += b1v; d2 += b0; d3 += b1v;
            if constexpr (MODE == 1) {
                d0 = fmaxf(d0, 0.f); d1 = fmaxf(d1, 0.f);
                d2 = fmaxf(d2, 0.f); d3 = fmaxf(d3, 0.f);
            }
        }
        if (r0 < NN) {
            *(float2*)(Out + (size_t)r0 * NOUT + cc) = make_float2(d0, d1);
            if constexpr (WH) {
                __half2 h = __floats2half2_rn(d0, d1);
                *(__half2*)(g_Ph + (size_t)r0 * HID + cc) = h;
            }
        }
        if (r1 < NN) {
            *(float2*)(Out + (size_t)r1 * NOUT + cc) = make_float2(d2, d3);
            if constexpr (WH) {
                __half2 h = __floats2half2_rn(d2, d3);
                *(__half2*)(g_Ph + (size_t)r1 * HID + cc) = h;
            }
        }
    }
}

// ---------------- host launcher ---------------------------------------------
extern "C" void kernel_launch(void* const* d_in, const int* in_sizes, int n_in,
                              void* d_out, int out_size) {
    const float* x    = (const float*)d_in[0];
    const int*   ei   = (const int*)d_in[1];
    const float* ew   = (const float*)d_in[2];
    const float* eps  = (const float*)d_in[3];
    const float* W1_0 = (const float*)d_in[4];
    const float* b1_0 = (const float*)d_in[5];
    const float* W1_r = (const float*)d_in[6];
    const float* b1_r = (const float*)d_in[7];
    const float* W2   = (const float*)d_in[8];
    const float* b2   = (const float*)d_in[9];
    const float* gam  = (const float*)d_in[10];
    const float* bet  = (const float*)d_in[11];
    const float* mean = (const float*)d_in[12];
    const float* var  = (const float*)d_in[13];
    const float* l2W  = (const float*)d_in[14];
    const float* l2b  = (const float*)d_in[15];
    float* out = (float*)d_out;

    float *P, *Z, *XS;
    cudaGetSymbolAddress((void**)&P, g_P);
    cudaGetSymbolAddress((void**)&Z, g_Z);
    cudaGetSymbolAddress((void**)&XS, g_xs);
    float* xs0 = XS;
    float* xs1 = XS + (size_t)NN * HID;
    float* xs2 = XS + 2 * (size_t)NN * HID;

    const int EBL = (NE + 255) / 256;      // 3907
    const int AB  = (NN * 16) / 256;       // 6250 (exact)

    // ----- init + fused {input projection || edge scatter} -----
    init_k<<<NB, 256>>>(ei);
    gemm_k<128, 64, 0, 1, 1><<<GRIDB + EBL, 256>>>(
        x, 0, 0, W1_0, 0, P, ei, ew);

    // ----- layer 0 -----
    agg_k<<<AB, 256>>>(P, Z, b1_0, gam, bet, mean, var, eps);
    gemm_k<64, 64, 1, 0, 0><<<GRIDB, 256>>>(
        Z, 0, 0, W2, b2, xs0, 0, 0);
    // ----- layer 1 -----
    gemm_k<64, 64, 0, 0, 1><<<GRIDB, 256>>>(
        xs0, 0, 0, W1_r, 0, P, 0, 0);
    agg_k<<<AB, 256>>>(P, Z, b1_r, gam + 64, bet + 64, mean + 64, var + 64,
                       eps + 1);
    gemm_k<64, 64, 1, 0, 0><<<GRIDB, 256>>>(
        Z, 0, 0, W2 + 4096, b2 + 64, xs1, 0, 0);
    // ----- layer 2 -----
    gemm_k<64, 64, 0, 0, 1><<<GRIDB, 256>>>(
        xs1, 0, 0, W1_r + 4096, 0, P, 0, 0);
    agg_k<<<AB, 256>>>(P, Z, b1_r + 64, gam + 128, bet + 128, mean + 128,
                       var + 128, eps + 2);
    gemm_k<64, 64, 1, 0, 0><<<GRIDB, 256>>>(
        Z, 0, 0, W2 + 8192, b2 + 128, xs2, 0, 0);
    // ----- final projection (concat fused) -----
    gemm_k<192, 32, 2, 0, 0><<<GRIDB, 256>>>(
        xs0, xs1, xs2, l2W, l2b, out, 0, 0);
}